// round 9
// baseline (speedup 1.0000x reference)
#include <cuda_runtime.h>
#include <cuda_fp16.h>
#include <mma.h>
#include <cstdint>
using namespace nvcuda;

#define NNODES 2048   // B*N
#define HD     768
#define DEG    32
#define NPB    256
#define RREL   64
#define NH     12

// Scratch (no cudaMalloc allowed)
__device__ __half g_Qh[NNODES * HD];
__device__ __half g_Kh[NNODES * HD];
__device__ __half g_Vh[NNODES * HD];
__device__ __half g_Xh[NNODES * HD];
__device__ __half g_Wh[3 * HD * HD];
__device__ __half g_Ekh[RREL * HD];
__device__ __half g_Evh[RREL * HD];
__device__ float  g_S2[NNODES * HD];   // [s][h*64+r]
__device__ __half g_Ph[NNODES * HD];   // [s][h*64+r]

// ---------------------------------------------------------------------------
// Kernel 0: fp32 -> fp16 conversion, one float4 per thread.
// z: 0..3 = X quarters, 4..6 = Wq/Wk/Wv, 7 = Ek|Ev
// ---------------------------------------------------------------------------
#define XQ4  (NNODES * HD / 16)
#define WQ4  (HD * HD / 4)
#define EQ4  (RREL * HD / 4)

__global__ __launch_bounds__(256) void cvt_f2h(
    const float* __restrict__ X,
    const float* __restrict__ Wq, const float* __restrict__ Wk,
    const float* __restrict__ Wv,
    const float* __restrict__ Ek, const float* __restrict__ Ev)
{
    const int z = blockIdx.y;
    const int idx = blockIdx.x * 256 + threadIdx.x;
    const float* src;
    __half2* dst;
    int off;
    if (z < 4) {
        if (idx >= XQ4) return;
        src = X + (size_t)z * XQ4 * 4;
        dst = (__half2*)(g_Xh + (size_t)z * XQ4 * 4);
        off = idx;
    } else if (z < 7) {
        if (idx >= WQ4) return;
        src = (z == 4) ? Wq : (z == 5) ? Wk : Wv;
        dst = (__half2*)(g_Wh + (size_t)(z - 4) * HD * HD);
        off = idx;
    } else {
        if (idx >= 2 * EQ4) return;
        if (idx < EQ4) { src = Ek; dst = (__half2*)g_Ekh; off = idx; }
        else           { src = Ev; dst = (__half2*)g_Evh; off = idx - EQ4; }
    }
    float4 v = ((const float4*)src)[off];
    dst[2 * off]     = __floats2half2_rn(v.x, v.y);
    dst[2 * off + 1] = __floats2half2_rn(v.z, v.w);
}

// ---------------------------------------------------------------------------
// Kernel 1: QKV projection GEMM (fp16 wmma, fp32 acc), fp16 outputs.
// ---------------------------------------------------------------------------
#define BM 128
#define BN 128
#define BK 32
#define PA 40
#define PB 136
#define PC 132

#define A_BYTES (2 * BM * PA * 2)
#define C_BYTES (BM * PC * 4)
#define GEMM_SMEM (C_BYTES)

__device__ __forceinline__ void cpa16(void* s, const void* g) {
    unsigned sa = (unsigned)__cvta_generic_to_shared(s);
    asm volatile("cp.async.cg.shared.global [%0], [%1], 16;" :: "r"(sa), "l"(g));
}

__global__ void __launch_bounds__(256) qkv_gemm(
    const float* __restrict__ bq, const float* __restrict__ bk,
    const float* __restrict__ bv)
{
    extern __shared__ __align__(16) unsigned char smem_raw[];
    __half (*As)[BM][PA] = reinterpret_cast<__half (*)[BM][PA]>(smem_raw);
    __half (*Bs)[BK][PB] = reinterpret_cast<__half (*)[BK][PB]>(smem_raw + A_BYTES);
    float (*Cs)[PC]      = reinterpret_cast<float (*)[PC]>(smem_raw);

    const int z = blockIdx.z;
    const __half* W   = g_Wh + (size_t)z * HD * HD;
    const float* bias = (z == 0) ? bq : (z == 1) ? bk : bv;
    __half* Ch        = (z == 0) ? g_Qh : (z == 1) ? g_Kh : g_Vh;

    const int tid  = threadIdx.x;
    const int warp = tid >> 5;
    const int wm   = (warp >> 1) * 32;
    const int wn   = (warp & 1) * 64;
    const int rowBase = blockIdx.x * BM;
    const int colBase = blockIdx.y * BN;

    wmma::fragment<wmma::accumulator, 16, 16, 16, float> cf[2][4];
    #pragma unroll
    for (int i = 0; i < 2; i++)
        #pragma unroll
        for (int j = 0; j < 4; j++)
            wmma::fill_fragment(cf[i][j], 0.0f);

    auto load_tiles = [&](int buf, int k0) {
        #pragma unroll
        for (int q = 0; q < 2; q++) {
            int idx = tid + 256 * q;
            int m = idx >> 2, c = idx & 3;
            cpa16(&As[buf][m][8 * c],
                  &g_Xh[(size_t)(rowBase + m) * HD + k0 + 8 * c]);
        }
        #pragma unroll
        for (int q = 0; q < 2; q++) {
            int idx = tid + 256 * q;
            int kk = idx >> 4, c = idx & 15;
            cpa16(&Bs[buf][kk][8 * c],
                  &W[(size_t)(k0 + kk) * HD + colBase + 8 * c]);
        }
        asm volatile("cp.async.commit_group;");
    };

    load_tiles(0, 0);

    const int NIT = HD / BK;
    for (int it = 0; it < NIT; ++it) {
        const int buf = it & 1;
        if (it + 1 < NIT) {
            load_tiles(buf ^ 1, (it + 1) * BK);
            asm volatile("cp.async.wait_group 1;");
        } else {
            asm volatile("cp.async.wait_group 0;");
        }
        __syncthreads();

        #pragma unroll
        for (int kk = 0; kk < BK; kk += 16) {
            wmma::fragment<wmma::matrix_a, 16, 16, 16, __half, wmma::row_major> a[2];
            wmma::fragment<wmma::matrix_b, 16, 16, 16, __half, wmma::row_major> b[4];
            wmma::load_matrix_sync(a[0], &As[buf][wm][kk], PA);
            wmma::load_matrix_sync(a[1], &As[buf][wm + 16][kk], PA);
            #pragma unroll
            for (int j = 0; j < 4; j++)
                wmma::load_matrix_sync(b[j], &Bs[buf][kk][wn + 16 * j], PB);
            #pragma unroll
            for (int i = 0; i < 2; i++)
                #pragma unroll
                for (int j = 0; j < 4; j++)
                    wmma::mma_sync(cf[i][j], a[i], b[j], cf[i][j]);
        }
        __syncthreads();
    }

    #pragma unroll
    for (int i = 0; i < 2; i++)
        #pragma unroll
        for (int j = 0; j < 4; j++)
            wmma::store_matrix_sync(&Cs[wm + 16 * i][wn + 16 * j], cf[i][j], PC,
                                    wmma::mem_row_major);
    __syncthreads();

    #pragma unroll
    for (int q = 0; q < 16; q++) {
        int idx = tid + 256 * q;
        int m = idx >> 5, c = idx & 31;
        float4 v  = *(const float4*)&Cs[m][4 * c];
        float4 bb = *(const float4*)&bias[colBase + 4 * c];
        __half2 h0 = __floats2half2_rn(v.x + bb.x, v.y + bb.y);
        __half2 h1 = __floats2half2_rn(v.z + bb.z, v.w + bb.w);
        __half2* dst = (__half2*)&Ch[(size_t)(rowBase + m) * HD + colBase + 4 * c];
        dst[0] = h0;
        dst[1] = h1;
    }
}

// ---------------------------------------------------------------------------
// Kernel S2: S2[s][h*64+r] = sum_k Qh[s][h*64+k] * Ekh[r][h*64+k]
// grid (16, 12); 128 threads; CTA does 128 rows x 64 r for one head.
// ---------------------------------------------------------------------------
__global__ __launch_bounds__(128) void s2_gemm()
{
    __shared__ __half As[128][72];
    __shared__ __half Bs[64][72];   // Bs[r][k]
    const int h = blockIdx.y;
    const int rowBase = blockIdx.x * 128;
    const int tid = threadIdx.x, warp = tid >> 5;

    for (int idx = tid; idx < 128 * 8; idx += 128) {
        int m = idx >> 3, c = idx & 7;
        *(uint4*)&As[m][8 * c] =
            *(const uint4*)&g_Qh[(size_t)(rowBase + m) * HD + h * 64 + 8 * c];
    }
    for (int idx = tid; idx < 64 * 8; idx += 128) {
        int r = idx >> 3, c = idx & 7;
        *(uint4*)&Bs[r][8 * c] =
            *(const uint4*)&g_Ekh[(size_t)r * HD + h * 64 + 8 * c];
    }
    __syncthreads();

    wmma::fragment<wmma::accumulator, 16, 16, 16, float> cf[2][4];
    #pragma unroll
    for (int i = 0; i < 2; i++)
        #pragma unroll
        for (int j = 0; j < 4; j++)
            wmma::fill_fragment(cf[i][j], 0.0f);

    #pragma unroll
    for (int k0 = 0; k0 < 64; k0 += 16) {
        wmma::fragment<wmma::matrix_a, 16, 16, 16, __half, wmma::row_major> a[2];
        wmma::fragment<wmma::matrix_b, 16, 16, 16, __half, wmma::col_major> b[4];
        wmma::load_matrix_sync(a[0], &As[warp * 32][k0], 72);
        wmma::load_matrix_sync(a[1], &As[warp * 32 + 16][k0], 72);
        #pragma unroll
        for (int j = 0; j < 4; j++)
            wmma::load_matrix_sync(b[j], &Bs[16 * j][k0], 72);
        #pragma unroll
        for (int i = 0; i < 2; i++)
            #pragma unroll
            for (int j = 0; j < 4; j++)
                wmma::mma_sync(cf[i][j], a[i], b[j], cf[i][j]);
    }
    #pragma unroll
    for (int i = 0; i < 2; i++)
        #pragma unroll
        for (int j = 0; j < 4; j++)
            wmma::store_matrix_sync(
                &g_S2[(size_t)(rowBase + warp * 32 + 16 * i) * HD + h * 64 + 16 * j],
                cf[i][j], HD, wmma::mem_row_major);
}

// ---------------------------------------------------------------------------
// Kernel EV: out[s][h*64+t] += sum_r Ph[s][h*64+r] * Evh[r][h*64+t]
// ---------------------------------------------------------------------------
__global__ __launch_bounds__(128) void ev_gemm(float* __restrict__ out)
{
    __shared__ __half As[128][72];
    __shared__ __half Bs[64][72];   // Bs[r][t]
    const int h = blockIdx.y;
    const int rowBase = blockIdx.x * 128;
    const int tid = threadIdx.x, warp = tid >> 5;

    for (int idx = tid; idx < 128 * 8; idx += 128) {
        int m = idx >> 3, c = idx & 7;
        *(uint4*)&As[m][8 * c] =
            *(const uint4*)&g_Ph[(size_t)(rowBase + m) * HD + h * 64 + 8 * c];
    }
    for (int idx = tid; idx < 64 * 8; idx += 128) {
        int r = idx >> 3, c = idx & 7;
        *(uint4*)&Bs[r][8 * c] =
            *(const uint4*)&g_Evh[(size_t)r * HD + h * 64 + 8 * c];
    }
    __syncthreads();

    wmma::fragment<wmma::accumulator, 16, 16, 16, float> cf[2][4];
    #pragma unroll
    for (int i = 0; i < 2; i++)
        #pragma unroll
        for (int j = 0; j < 4; j++)
            wmma::load_matrix_sync(cf[i][j],
                &out[(size_t)(rowBase + warp * 32 + 16 * i) * HD + h * 64 + 16 * j],
                HD, wmma::mem_row_major);

    #pragma unroll
    for (int k0 = 0; k0 < 64; k0 += 16) {
        wmma::fragment<wmma::matrix_a, 16, 16, 16, __half, wmma::row_major> a[2];
        wmma::fragment<wmma::matrix_b, 16, 16, 16, __half, wmma::row_major> b[4];
        wmma::load_matrix_sync(a[0], &As[warp * 32][k0], 72);
        wmma::load_matrix_sync(a[1], &As[warp * 32 + 16][k0], 72);
        #pragma unroll
        for (int j = 0; j < 4; j++)
            wmma::load_matrix_sync(b[j], &Bs[k0][16 * j], 72);
        #pragma unroll
        for (int i = 0; i < 2; i++)
            #pragma unroll
            for (int j = 0; j < 4; j++)
                wmma::mma_sync(cf[i][j], a[i], b[j], cf[i][j]);
    }
    #pragma unroll
    for (int i = 0; i < 2; i++)
        #pragma unroll
        for (int j = 0; j < 4; j++)
            wmma::store_matrix_sync(
                &out[(size_t)(rowBase + warp * 32 + 16 * i) * HD + h * 64 + 16 * j],
                cf[i][j], HD, wmma::mem_row_major);
}

// ---------------------------------------------------------------------------
// Kernel 2: grouped edge attention. CTA handles G=4 stride-7 segments of one
// batch; stages the union of UN=35 K/V rows in smem (31/32 row sharing).
// Ek term comes from precomputed S2; Ev term accumulated into P for ev_gemm.
// ---------------------------------------------------------------------------
#define G  4
#define UN (G + 31)   // 35

// smem offsets (bytes)
#define EO_K   0
#define EO_V   (UN * HD * 2)             // 53760
#define EO_Q   (2 * UN * HD * 2)         // 107520
#define EO_ATT (EO_Q + HD * 2)           // 109056
#define EO_P   (EO_ATT + 32 * 13 * 4)    // 110720
#define EO_INV (EO_P + HD * 4)           // 113792
#define EO_MS  (EO_INV + 512)            // 114304
#define EO_RS  (EO_MS + 128)             // 114432
#define EDGE_SMEM (EO_RS + 128)          // 114560

__global__ __launch_bounds__(512, 2) void edge_attn2(
    const int* __restrict__ ej, const int* __restrict__ er,
    float* __restrict__ out)
{
    extern __shared__ __align__(16) unsigned char sm[];
    __half (*Ks)[HD] = (__half(*)[HD])(sm + EO_K);
    __half (*Vs)[HD] = (__half(*)[HD])(sm + EO_V);
    __half* qs       = (__half*)(sm + EO_Q);
    float (*att)[13] = (float(*)[13])(sm + EO_ATT);
    float* P         = (float*)(sm + EO_P);
    short* inv       = (short*)(sm + EO_INV);
    int* msArr       = (int*)(sm + EO_MS);
    int* rsArr       = (int*)(sm + EO_RS);

    const int tid  = threadIdx.x;
    const int warp = tid >> 5;
    const int lane = tid & 31;
    const int b  = blockIdx.x >> 6;       // 64 CTAs per batch (256/G)
    const int t0 = (blockIdx.x & 63) * G; // stride-7-space base

    if (tid < UN) {
        int j = (1 + 7 * (t0 + tid)) & 255;
        inv[j] = (short)tid;
    }
    // stage K and V union rows (each row = 96 uint4, warp-aligned)
    for (int idx = tid; idx < UN * 96; idx += 512) {
        int m = idx / 96, c = idx % 96;
        int j = (1 + 7 * (t0 + m)) & 255;
        ((uint4*)Ks[m])[c] = ((const uint4*)(g_Kh + (size_t)(b * 256 + j) * HD))[c];
    }
    for (int idx = tid; idx < UN * 96; idx += 512) {
        int m = idx / 96, c = idx % 96;
        int j = (1 + 7 * (t0 + m)) & 255;
        ((uint4*)Vs[m])[c] = ((const uint4*)(g_Vh + (size_t)(b * 256 + j) * HD))[c];
    }
    __syncthreads();

    for (int g = 0; g < G; g++) {
        const int i = (7 * (t0 + g)) & 255;
        const int s = b * 256 + i;

        if (tid < 96)
            ((uint4*)qs)[tid] = ((const uint4*)(g_Qh + (size_t)s * HD))[tid];
        if (tid < 32) {
            int e = s * DEG + tid;
            msArr[tid] = inv[ej[e]];
            rsArr[tid] = er[e];
        }
        if (tid < 256) { P[tid] = 0.f; P[tid + 256] = 0.f; P[tid + 512] = 0.f; }
        __syncthreads();

        // ---- logits: 16 warps x 2 edges; head = 4u + (lane>>3) ----
        for (int d = warp; d < DEG; d += 16) {
            const uint4* krow = (const uint4*)Ks[msArr[d]];
            const uint4* qrow = (const uint4*)qs;
            float part[3];
            #pragma unroll
            for (int u = 0; u < 3; u++) {
                int i4 = u * 32 + lane;
                uint4 k8 = krow[i4];
                uint4 q8 = qrow[i4];
                float acc = 0.f;
                #pragma unroll
                for (int w = 0; w < 4; w++) {
                    float2 kf = __half22float2(((const __half2*)&k8)[w]);
                    float2 qf = __half22float2(((const __half2*)&q8)[w]);
                    acc += qf.x * kf.x + qf.y * kf.y;
                }
                part[u] = acc;
            }
            #pragma unroll
            for (int off = 4; off >= 1; off >>= 1)
                #pragma unroll
                for (int u = 0; u < 3; u++)
                    part[u] += __shfl_xor_sync(0xffffffffu, part[u], off);
            if ((lane & 7) == 0) {
                int r = rsArr[d];
                #pragma unroll
                for (int u = 0; u < 3; u++) {
                    int h = 4 * u + (lane >> 3);
                    att[d][h] = (part[u] + g_S2[(size_t)s * HD + h * 64 + r]) * 0.125f;
                }
            }
        }
        __syncthreads();

        // ---- softmax (warp h, lane d) + P scatter ----
        if (warp < NH) {
            float lg = att[lane][warp];
            float m = lg;
            #pragma unroll
            for (int off = 16; off >= 1; off >>= 1)
                m = fmaxf(m, __shfl_xor_sync(0xffffffffu, m, off));
            float ex = __expf(lg - m);
            float ssum = ex;
            #pragma unroll
            for (int off = 16; off >= 1; off >>= 1)
                ssum += __shfl_xor_sync(0xffffffffu, ssum, off);
            float a = ex / ssum;
            att[lane][warp] = a;
            atomicAdd(&P[warp * 64 + rsArr[lane]], a);
        }
        __syncthreads();

        // ---- V accumulate (threads < 384 own 2 elems) + P writeback ----
        if (tid < 384) {
            const int t = tid * 2;
            const int h = tid >> 5;
            float2 acc = make_float2(0.f, 0.f);
            #pragma unroll 4
            for (int d = 0; d < DEG; d++) {
                float a = att[d][h];
                float2 vf = __half22float2(*(const __half2*)&Vs[msArr[d]][t]);
                acc.x += a * vf.x;
                acc.y += a * vf.y;
            }
            *(float2*)(out + (size_t)s * HD + t) = acc;
            ((__half2*)(g_Ph + (size_t)s * HD))[tid] =
                __floats2half2_rn(P[2 * tid], P[2 * tid + 1]);
        }
        __syncthreads();
    }
}

// ---------------------------------------------------------------------------
extern "C" void kernel_launch(void* const* d_in, const int* in_sizes, int n_in,
                              void* d_out, int out_size)
{
    const float* x  = (const float*)d_in[0];
    const int* edges = (const int*)d_in[1];
    const float* Wq = (const float*)d_in[2];
    const float* bq = (const float*)d_in[3];
    const float* Wk = (const float*)d_in[4];
    const float* bk = (const float*)d_in[5];
    const float* Wv = (const float*)d_in[6];
    const float* bv = (const float*)d_in[7];
    const float* Ek = (const float*)d_in[8];
    const float* Ev = (const float*)d_in[9];
    float* out = (float*)d_out;

    const size_t E = (size_t)in_sizes[1] / 4;

    cudaFuncSetAttribute(qkv_gemm, cudaFuncAttributeMaxDynamicSharedMemorySize,
                         GEMM_SMEM);
    cudaFuncSetAttribute(edge_attn2, cudaFuncAttributeMaxDynamicSharedMemorySize,
                         EDGE_SMEM);

    cvt_f2h<<<dim3(576, 8), 256>>>(x, Wq, Wk, Wv, Ek, Ev);

    dim3 ggrid(NNODES / BM, HD / BN, 3);
    qkv_gemm<<<ggrid, 256, GEMM_SMEM>>>(bq, bk, bv);

    s2_gemm<<<dim3(NNODES / 128, NH), 128>>>();

    edge_attn2<<<NNODES / G, 512, EDGE_SMEM>>>(edges + 2 * E, edges + 3 * E, out);

    ev_gemm<<<dim3(NNODES / 128, NH), 128>>>(out);
}

// round 11
// speedup vs baseline: 1.4771x; 1.4771x over previous
#include <cuda_runtime.h>
#include <cuda_fp16.h>
#include <mma.h>
#include <cstdint>
using namespace nvcuda;

#define NNODES 2048   // B*N
#define HD     768
#define DEG    32
#define NPB    256
#define RREL   64
#define NH     12

// Scratch (no cudaMalloc allowed)
__device__ __half g_Qh[NNODES * HD];
__device__ __half g_Kh[NNODES * HD];
__device__ __half g_Vh[NNODES * HD];
__device__ __half g_Xh[NNODES * HD];
__device__ __half g_Wh[3 * HD * HD];
__device__ __half g_Ekh[RREL * HD];
__device__ __half g_Evh[RREL * HD];
__device__ float  g_S2[NNODES * HD];   // [s][h*64+r]
__device__ __half g_Ph[NNODES * HD];   // [s][h*64+r]

// ---------------------------------------------------------------------------
// Kernel 0: fp32 -> fp16, one float4 per thread.
// ---------------------------------------------------------------------------
#define XQ4  (NNODES * HD / 16)
#define WQ4  (HD * HD / 4)
#define EQ4  (RREL * HD / 4)

__global__ __launch_bounds__(256) void cvt_f2h(
    const float* __restrict__ X,
    const float* __restrict__ Wq, const float* __restrict__ Wk,
    const float* __restrict__ Wv,
    const float* __restrict__ Ek, const float* __restrict__ Ev)
{
    const int z = blockIdx.y;
    const int idx = blockIdx.x * 256 + threadIdx.x;
    const float* src;
    __half2* dst;
    int off;
    if (z < 4) {
        if (idx >= XQ4) return;
        src = X + (size_t)z * XQ4 * 4;
        dst = (__half2*)(g_Xh + (size_t)z * XQ4 * 4);
        off = idx;
    } else if (z < 7) {
        if (idx >= WQ4) return;
        src = (z == 4) ? Wq : (z == 5) ? Wk : Wv;
        dst = (__half2*)(g_Wh + (size_t)(z - 4) * HD * HD);
        off = idx;
    } else {
        if (idx >= 2 * EQ4) return;
        if (idx < EQ4) { src = Ek; dst = (__half2*)g_Ekh; off = idx; }
        else           { src = Ev; dst = (__half2*)g_Evh; off = idx - EQ4; }
    }
    float4 v = ((const float4*)src)[off];
    dst[2 * off]     = __floats2half2_rn(v.x, v.y);
    dst[2 * off + 1] = __floats2half2_rn(v.z, v.w);
}

// ---------------------------------------------------------------------------
// Kernel 1: QKV projection GEMM (fp16 wmma, fp32 acc), fp16 outputs.
// ---------------------------------------------------------------------------
#define BM 128
#define BN 128
#define BK 32
#define PA 40
#define PB 136
#define PC 132

#define A_BYTES (2 * BM * PA * 2)
#define C_BYTES (BM * PC * 4)
#define GEMM_SMEM (C_BYTES)

__device__ __forceinline__ void cpa16(void* s, const void* g) {
    unsigned sa = (unsigned)__cvta_generic_to_shared(s);
    asm volatile("cp.async.cg.shared.global [%0], [%1], 16;" :: "r"(sa), "l"(g));
}

__global__ void __launch_bounds__(256) qkv_gemm(
    const float* __restrict__ bq, const float* __restrict__ bk,
    const float* __restrict__ bv)
{
    extern __shared__ __align__(16) unsigned char smem_raw[];
    __half (*As)[BM][PA] = reinterpret_cast<__half (*)[BM][PA]>(smem_raw);
    __half (*Bs)[BK][PB] = reinterpret_cast<__half (*)[BK][PB]>(smem_raw + A_BYTES);
    float (*Cs)[PC]      = reinterpret_cast<float (*)[PC]>(smem_raw);

    const int z = blockIdx.z;
    const __half* W   = g_Wh + (size_t)z * HD * HD;
    const float* bias = (z == 0) ? bq : (z == 1) ? bk : bv;
    __half* Ch        = (z == 0) ? g_Qh : (z == 1) ? g_Kh : g_Vh;

    const int tid  = threadIdx.x;
    const int warp = tid >> 5;
    const int wm   = (warp >> 1) * 32;
    const int wn   = (warp & 1) * 64;
    const int rowBase = blockIdx.x * BM;
    const int colBase = blockIdx.y * BN;

    wmma::fragment<wmma::accumulator, 16, 16, 16, float> cf[2][4];
    #pragma unroll
    for (int i = 0; i < 2; i++)
        #pragma unroll
        for (int j = 0; j < 4; j++)
            wmma::fill_fragment(cf[i][j], 0.0f);

    auto load_tiles = [&](int buf, int k0) {
        #pragma unroll
        for (int q = 0; q < 2; q++) {
            int idx = tid + 256 * q;
            int m = idx >> 2, c = idx & 3;
            cpa16(&As[buf][m][8 * c],
                  &g_Xh[(size_t)(rowBase + m) * HD + k0 + 8 * c]);
        }
        #pragma unroll
        for (int q = 0; q < 2; q++) {
            int idx = tid + 256 * q;
            int kk = idx >> 4, c = idx & 15;
            cpa16(&Bs[buf][kk][8 * c],
                  &W[(size_t)(k0 + kk) * HD + colBase + 8 * c]);
        }
        asm volatile("cp.async.commit_group;");
    };

    load_tiles(0, 0);

    const int NIT = HD / BK;
    for (int it = 0; it < NIT; ++it) {
        const int buf = it & 1;
        if (it + 1 < NIT) {
            load_tiles(buf ^ 1, (it + 1) * BK);
            asm volatile("cp.async.wait_group 1;");
        } else {
            asm volatile("cp.async.wait_group 0;");
        }
        __syncthreads();

        #pragma unroll
        for (int kk = 0; kk < BK; kk += 16) {
            wmma::fragment<wmma::matrix_a, 16, 16, 16, __half, wmma::row_major> a[2];
            wmma::fragment<wmma::matrix_b, 16, 16, 16, __half, wmma::row_major> b[4];
            wmma::load_matrix_sync(a[0], &As[buf][wm][kk], PA);
            wmma::load_matrix_sync(a[1], &As[buf][wm + 16][kk], PA);
            #pragma unroll
            for (int j = 0; j < 4; j++)
                wmma::load_matrix_sync(b[j], &Bs[buf][kk][wn + 16 * j], PB);
            #pragma unroll
            for (int i = 0; i < 2; i++)
                #pragma unroll
                for (int j = 0; j < 4; j++)
                    wmma::mma_sync(cf[i][j], a[i], b[j], cf[i][j]);
        }
        __syncthreads();
    }

    #pragma unroll
    for (int i = 0; i < 2; i++)
        #pragma unroll
        for (int j = 0; j < 4; j++)
            wmma::store_matrix_sync(&Cs[wm + 16 * i][wn + 16 * j], cf[i][j], PC,
                                    wmma::mem_row_major);
    __syncthreads();

    #pragma unroll
    for (int q = 0; q < 16; q++) {
        int idx = tid + 256 * q;
        int m = idx >> 5, c = idx & 31;
        float4 v  = *(const float4*)&Cs[m][4 * c];
        float4 bb = *(const float4*)&bias[colBase + 4 * c];
        __half2 h0 = __floats2half2_rn(v.x + bb.x, v.y + bb.y);
        __half2 h1 = __floats2half2_rn(v.z + bb.z, v.w + bb.w);
        __half2* dst = (__half2*)&Ch[(size_t)(rowBase + m) * HD + colBase + 4 * c];
        dst[0] = h0;
        dst[1] = h1;
    }
}

// ---------------------------------------------------------------------------
// Kernel S2: S2[s][h*64+r] = sum_k Qh[s][h*64+k] * Ekh[r][h*64+k]
// ---------------------------------------------------------------------------
__global__ __launch_bounds__(128) void s2_gemm()
{
    __shared__ __half As[128][72];
    __shared__ __half Bs[64][72];
    const int h = blockIdx.y;
    const int rowBase = blockIdx.x * 128;
    const int tid = threadIdx.x, warp = tid >> 5;

    for (int idx = tid; idx < 128 * 8; idx += 128) {
        int m = idx >> 3, c = idx & 7;
        *(uint4*)&As[m][8 * c] =
            *(const uint4*)&g_Qh[(size_t)(rowBase + m) * HD + h * 64 + 8 * c];
    }
    for (int idx = tid; idx < 64 * 8; idx += 128) {
        int r = idx >> 3, c = idx & 7;
        *(uint4*)&Bs[r][8 * c] =
            *(const uint4*)&g_Ekh[(size_t)r * HD + h * 64 + 8 * c];
    }
    __syncthreads();

    wmma::fragment<wmma::accumulator, 16, 16, 16, float> cf[2][4];
    #pragma unroll
    for (int i = 0; i < 2; i++)
        #pragma unroll
        for (int j = 0; j < 4; j++)
            wmma::fill_fragment(cf[i][j], 0.0f);

    #pragma unroll
    for (int k0 = 0; k0 < 64; k0 += 16) {
        wmma::fragment<wmma::matrix_a, 16, 16, 16, __half, wmma::row_major> a[2];
        wmma::fragment<wmma::matrix_b, 16, 16, 16, __half, wmma::col_major> b[4];
        wmma::load_matrix_sync(a[0], &As[warp * 32][k0], 72);
        wmma::load_matrix_sync(a[1], &As[warp * 32 + 16][k0], 72);
        #pragma unroll
        for (int j = 0; j < 4; j++)
            wmma::load_matrix_sync(b[j], &Bs[16 * j][k0], 72);
        #pragma unroll
        for (int i = 0; i < 2; i++)
            #pragma unroll
            for (int j = 0; j < 4; j++)
                wmma::mma_sync(cf[i][j], a[i], b[j], cf[i][j]);
    }
    #pragma unroll
    for (int i = 0; i < 2; i++)
        #pragma unroll
        for (int j = 0; j < 4; j++)
            wmma::store_matrix_sync(
                &g_S2[(size_t)(rowBase + warp * 32 + 16 * i) * HD + h * 64 + 16 * j],
                cf[i][j], HD, wmma::mem_row_major);
}

// ---------------------------------------------------------------------------
// Kernel EV: out[s][h*64+t] += sum_r Ph[s][h*64+r] * Evh[r][h*64+t]
// ---------------------------------------------------------------------------
__global__ __launch_bounds__(128) void ev_gemm(float* __restrict__ out)
{
    __shared__ __half As[128][72];
    __shared__ __half Bs[64][72];
    const int h = blockIdx.y;
    const int rowBase = blockIdx.x * 128;
    const int tid = threadIdx.x, warp = tid >> 5;

    for (int idx = tid; idx < 128 * 8; idx += 128) {
        int m = idx >> 3, c = idx & 7;
        *(uint4*)&As[m][8 * c] =
            *(const uint4*)&g_Ph[(size_t)(rowBase + m) * HD + h * 64 + 8 * c];
    }
    for (int idx = tid; idx < 64 * 8; idx += 128) {
        int r = idx >> 3, c = idx & 7;
        *(uint4*)&Bs[r][8 * c] =
            *(const uint4*)&g_Evh[(size_t)r * HD + h * 64 + 8 * c];
    }
    __syncthreads();

    wmma::fragment<wmma::accumulator, 16, 16, 16, float> cf[2][4];
    #pragma unroll
    for (int i = 0; i < 2; i++)
        #pragma unroll
        for (int j = 0; j < 4; j++)
            wmma::load_matrix_sync(cf[i][j],
                &out[(size_t)(rowBase + warp * 32 + 16 * i) * HD + h * 64 + 16 * j],
                HD, wmma::mem_row_major);

    #pragma unroll
    for (int k0 = 0; k0 < 64; k0 += 16) {
        wmma::fragment<wmma::matrix_a, 16, 16, 16, __half, wmma::row_major> a[2];
        wmma::fragment<wmma::matrix_b, 16, 16, 16, __half, wmma::row_major> b[4];
        wmma::load_matrix_sync(a[0], &As[warp * 32][k0], 72);
        wmma::load_matrix_sync(a[1], &As[warp * 32 + 16][k0], 72);
        #pragma unroll
        for (int j = 0; j < 4; j++)
            wmma::load_matrix_sync(b[j], &Bs[k0][16 * j], 72);
        #pragma unroll
        for (int i = 0; i < 2; i++)
            #pragma unroll
            for (int j = 0; j < 4; j++)
                wmma::mma_sync(cf[i][j], a[i], b[j], cf[i][j]);
    }
    #pragma unroll
    for (int i = 0; i < 2; i++)
        #pragma unroll
        for (int j = 0; j < 4; j++)
            wmma::store_matrix_sync(
                &out[(size_t)(rowBase + warp * 32 + 16 * i) * HD + h * 64 + 16 * j],
                cf[i][j], HD, wmma::mem_row_major);
}

// ---------------------------------------------------------------------------
// Kernel 2: banded attention. In permuted coords (i = 7t mod 256,
// j = 1+7u mod 256), segment t attends u in [t, t+31] -> sliding window 32.
// CTA = (ttile of 32 t-rows, head, batch). S = Qp@Kp^T (wmma), band softmax
// with S2 r-term, O = A@Vp (wmma). P bins accumulated for ev_gemm.
// ---------------------------------------------------------------------------
// smem offsets (bytes)
#define BO_Q    0                      // [32][72] half
#define BO_K    4608                   // [64][72] half
#define BO_V    13824                  // [64][72] half
#define BO_A    23040                  // [32][72] half
#define BO_S    27648                  // [32][68] float
#define BO_S2   36352                  // [32][64] float
#define BO_P    44544                  // [32][64] float
#define BO_RK   52736                  // [32][32] uint8
#define BAND_SMEM 53760

__global__ __launch_bounds__(128) void banded_attn(
    const int* __restrict__ ej, const int* __restrict__ er,
    float* __restrict__ out)
{
    extern __shared__ __align__(16) unsigned char sm[];
    __half (*Qs)[72]  = (__half(*)[72])(sm + BO_Q);
    __half (*Ks)[72]  = (__half(*)[72])(sm + BO_K);
    __half (*Vs)[72]  = (__half(*)[72])(sm + BO_V);
    __half (*Ah)[72]  = (__half(*)[72])(sm + BO_A);
    float (*Sf)[68]   = (float(*)[68])(sm + BO_S);
    float* S2s        = (float*)(sm + BO_S2);
    float* Pb         = (float*)(sm + BO_P);
    unsigned char* rk = (unsigned char*)(sm + BO_RK);

    const int tid  = threadIdx.x;
    const int warp = tid >> 5;
    const int t0 = blockIdx.x * 32;
    const int h  = blockIdx.y;
    const int b  = blockIdx.z;

    // ---- stage Q (32 rows), K/V (64 rows), head slice h*64 ----
    #pragma unroll
    for (int q = 0; q < 2; q++) {
        int idx = tid + 128 * q;          // 256 = 32*8
        int tp = idx >> 3, c = idx & 7;
        int i = (7 * (t0 + tp)) & 255;
        *(uint4*)&Qs[tp][8 * c] =
            *(const uint4*)&g_Qh[(size_t)(b * 256 + i) * HD + h * 64 + 8 * c];
    }
    #pragma unroll
    for (int q = 0; q < 4; q++) {
        int idx = tid + 128 * q;          // 512 = 64*8
        int uc = idx >> 3, c = idx & 7;
        int j = (1 + 7 * (t0 + uc)) & 255;
        const size_t go = (size_t)(b * 256 + j) * HD + h * 64 + 8 * c;
        *(uint4*)&Ks[uc][8 * c] = *(const uint4*)&g_Kh[go];
        *(uint4*)&Vs[uc][8 * c] = *(const uint4*)&g_Vh[go];
    }
    // ---- stage edges: band position + r per (t', d) ----
    #pragma unroll
    for (int q = 0; q < 8; q++) {
        int idx = tid + 128 * q;          // 1024 = 32*32
        int tp = idx >> 5, d = idx & 31;
        int t = t0 + tp;
        int i = (7 * t) & 255;
        int e = (b * 256 + i) * DEG + d;
        int jv = ej[e];
        int u = (183 * (jv - 1)) & 255;   // 7^-1 = 183 mod 256
        int k = (u - t) & 255;            // in [0,32)
        rk[tp * 32 + k] = (unsigned char)er[e];
    }
    // ---- stage S2 rows ----
    #pragma unroll
    for (int q = 0; q < 16; q++) {
        int idx = tid + 128 * q;          // 2048 = 32*64
        int tp = idx >> 6, r = idx & 63;
        int i = (7 * (t0 + tp)) & 255;
        S2s[idx] = g_S2[(size_t)(b * 256 + i) * HD + h * 64 + r];
    }
    // ---- zero A and P ----
    #pragma unroll
    for (int q = 0; q < 3; q++) {
        int idx = tid + 128 * q;          // 288 uint4 = 32*72 halves
        if (idx < 288) ((uint4*)Ah)[idx] = make_uint4(0, 0, 0, 0);
    }
    #pragma unroll
    for (int q = 0; q < 4; q++)
        ((uint4*)Pb)[tid + 128 * q] = make_uint4(0, 0, 0, 0);
    __syncthreads();

    // ---- GEMM1: Sf = Qs(32x64) @ Ks^T(64x64). warp w: rows (w&1)*16,
    //      cols (w>>1)*32 (two 16-wide frags) ----
    const int m0 = (warp & 1) * 16;
    const int n0 = (warp >> 1) * 32;
    {
        wmma::fragment<wmma::accumulator, 16, 16, 16, float> acc[2];
        wmma::fill_fragment(acc[0], 0.0f);
        wmma::fill_fragment(acc[1], 0.0f);
        #pragma unroll
        for (int k0 = 0; k0 < 64; k0 += 16) {
            wmma::fragment<wmma::matrix_a, 16, 16, 16, __half, wmma::row_major> a;
            wmma::fragment<wmma::matrix_b, 16, 16, 16, __half, wmma::col_major> bf[2];
            wmma::load_matrix_sync(a, &Qs[m0][k0], 72);
            wmma::load_matrix_sync(bf[0], &Ks[n0][k0], 72);
            wmma::load_matrix_sync(bf[1], &Ks[n0 + 16][k0], 72);
            wmma::mma_sync(acc[0], a, bf[0], acc[0]);
            wmma::mma_sync(acc[1], a, bf[1], acc[1]);
        }
        wmma::store_matrix_sync(&Sf[m0][n0], acc[0], 68, wmma::mem_row_major);
        wmma::store_matrix_sync(&Sf[m0][n0 + 16], acc[1], 68, wmma::mem_row_major);
    }
    __syncthreads();

    // ---- band softmax: 4 threads per row, 8 k each ----
    {
        const int tp = tid >> 2, qd = tid & 3;
        float ex[8];
        float mx = -1e30f;
        int rr[8];
        #pragma unroll
        for (int zl = 0; zl < 8; zl++) {
            int k = qd * 8 + zl;
            rr[zl] = rk[tp * 32 + k];
            ex[zl] = (Sf[tp][tp + k] + S2s[tp * 64 + rr[zl]]) * 0.125f;
            mx = fmaxf(mx, ex[zl]);
        }
        mx = fmaxf(mx, __shfl_xor_sync(0xffffffffu, mx, 1));
        mx = fmaxf(mx, __shfl_xor_sync(0xffffffffu, mx, 2));
        float sum = 0.f;
        #pragma unroll
        for (int zl = 0; zl < 8; zl++) {
            ex[zl] = __expf(ex[zl] - mx);
            sum += ex[zl];
        }
        sum += __shfl_xor_sync(0xffffffffu, sum, 1);
        sum += __shfl_xor_sync(0xffffffffu, sum, 2);
        const float inv = 1.0f / sum;
        #pragma unroll
        for (int zl = 0; zl < 8; zl++) {
            int k = qd * 8 + zl;
            float a = ex[zl] * inv;
            Ah[tp][tp + k] = __float2half(a);
            atomicAdd(&Pb[tp * 64 + rr[zl]], a);
        }
    }
    __syncthreads();

    // ---- GEMM2: Sf = Ah(32x64) @ Vs(64x64) ----
    {
        wmma::fragment<wmma::accumulator, 16, 16, 16, float> acc[2];
        wmma::fill_fragment(acc[0], 0.0f);
        wmma::fill_fragment(acc[1], 0.0f);
        #pragma unroll
        for (int k0 = 0; k0 < 64; k0 += 16) {
            wmma::fragment<wmma::matrix_a, 16, 16, 16, __half, wmma::row_major> a;
            wmma::fragment<wmma::matrix_b, 16, 16, 16, __half, wmma::row_major> bf[2];
            wmma::load_matrix_sync(a, &Ah[m0][k0], 72);
            wmma::load_matrix_sync(bf[0], &Vs[k0][n0], 72);
            wmma::load_matrix_sync(bf[1], &Vs[k0][n0 + 16], 72);
            wmma::mma_sync(acc[0], a, bf[0], acc[0]);
            wmma::mma_sync(acc[1], a, bf[1], acc[1]);
        }
        wmma::store_matrix_sync(&Sf[m0][n0], acc[0], 68, wmma::mem_row_major);
        wmma::store_matrix_sync(&Sf[m0][n0 + 16], acc[1], 68, wmma::mem_row_major);
    }
    __syncthreads();

    // ---- write out (permuted rows) + P (fp16) ----
    #pragma unroll
    for (int q = 0; q < 4; q++) {
        int idx = tid + 128 * q;          // 512 = 32*16 float4
        int tp = idx >> 4, c = idx & 15;
        int i = (7 * (t0 + tp)) & 255;
        float4 v = *(const float4*)&Sf[tp][4 * c];
        *(float4*)&out[(size_t)(b * 256 + i) * HD + h * 64 + 4 * c] = v;
    }
    #pragma unroll
    for (int q = 0; q < 8; q++) {
        int idx = tid + 128 * q;          // 1024 = 32*32 half2
        int tp = idx >> 5, rp = idx & 31;
        int i = (7 * (t0 + tp)) & 255;
        ((__half2*)&g_Ph[(size_t)(b * 256 + i) * HD + h * 64])[rp] =
            __floats2half2_rn(Pb[tp * 64 + 2 * rp], Pb[tp * 64 + 2 * rp + 1]);
    }
}

// ---------------------------------------------------------------------------
extern "C" void kernel_launch(void* const* d_in, const int* in_sizes, int n_in,
                              void* d_out, int out_size)
{
    const float* x  = (const float*)d_in[0];
    const int* edges = (const int*)d_in[1];
    const float* Wq = (const float*)d_in[2];
    const float* bq = (const float*)d_in[3];
    const float* Wk = (const float*)d_in[4];
    const float* bk = (const float*)d_in[5];
    const float* Wv = (const float*)d_in[6];
    const float* bv = (const float*)d_in[7];
    const float* Ek = (const float*)d_in[8];
    const float* Ev = (const float*)d_in[9];
    float* out = (float*)d_out;

    const size_t E = (size_t)in_sizes[1] / 4;

    cudaFuncSetAttribute(qkv_gemm, cudaFuncAttributeMaxDynamicSharedMemorySize,
                         GEMM_SMEM);
    cudaFuncSetAttribute(banded_attn, cudaFuncAttributeMaxDynamicSharedMemorySize,
                         BAND_SMEM);

    cvt_f2h<<<dim3(576, 8), 256>>>(x, Wq, Wk, Wv, Ek, Ev);

    dim3 ggrid(NNODES / BM, HD / BN, 3);
    qkv_gemm<<<ggrid, 256, GEMM_SMEM>>>(bq, bk, bv);

    s2_gemm<<<dim3(NNODES / 128, NH), 128>>>();

    banded_attn<<<dim3(NPB / 32, NH, 8), 128, BAND_SMEM>>>(
        edges + 2 * E, edges + 3 * E, out);

    ev_gemm<<<dim3(NNODES / 128, NH), 128>>>(out);
}

// round 12
// speedup vs baseline: 1.9515x; 1.3212x over previous
#include <cuda_runtime.h>
#include <cuda_fp16.h>
#include <mma.h>
#include <cstdint>
using namespace nvcuda;

#define NNODES 2048   // B*N
#define HD     768
#define DEG    32
#define NPB    256
#define RREL   64
#define NH     12

// Scratch (no cudaMalloc allowed)
__device__ __half g_Qh[NNODES * HD];
__device__ __half g_Kh[NNODES * HD];
__device__ __half g_Vh[NNODES * HD];
__device__ __half g_Xh[NNODES * HD];
__device__ __half g_Wh[3 * HD * HD];
__device__ __half g_Ekh[RREL * HD];
__device__ __half g_Evh[RREL * HD];

// ---------------------------------------------------------------------------
// Kernel 0: fp32 -> fp16, one float4 per thread.
// ---------------------------------------------------------------------------
#define XQ4  (NNODES * HD / 16)
#define WQ4  (HD * HD / 4)
#define EQ4  (RREL * HD / 4)

__global__ __launch_bounds__(256) void cvt_f2h(
    const float* __restrict__ X,
    const float* __restrict__ Wq, const float* __restrict__ Wk,
    const float* __restrict__ Wv,
    const float* __restrict__ Ek, const float* __restrict__ Ev)
{
    const int z = blockIdx.y;
    const int idx = blockIdx.x * 256 + threadIdx.x;
    const float* src;
    __half2* dst;
    int off;
    if (z < 4) {
        if (idx >= XQ4) return;
        src = X + (size_t)z * XQ4 * 4;
        dst = (__half2*)(g_Xh + (size_t)z * XQ4 * 4);
        off = idx;
    } else if (z < 7) {
        if (idx >= WQ4) return;
        src = (z == 4) ? Wq : (z == 5) ? Wk : Wv;
        dst = (__half2*)(g_Wh + (size_t)(z - 4) * HD * HD);
        off = idx;
    } else {
        if (idx >= 2 * EQ4) return;
        if (idx < EQ4) { src = Ek; dst = (__half2*)g_Ekh; off = idx; }
        else           { src = Ev; dst = (__half2*)g_Evh; off = idx - EQ4; }
    }
    float4 v = ((const float4*)src)[off];
    dst[2 * off]     = __floats2half2_rn(v.x, v.y);
    dst[2 * off + 1] = __floats2half2_rn(v.z, v.w);
}

// ---------------------------------------------------------------------------
// Kernel 1: QKV projection GEMM (fp16 wmma, fp32 acc), fp16 outputs.
// ---------------------------------------------------------------------------
#define BM 128
#define BN 128
#define BK 32
#define PA 40
#define PB 136
#define PC 132

#define A_BYTES (2 * BM * PA * 2)
#define C_BYTES (BM * PC * 4)
#define GEMM_SMEM (C_BYTES)

__device__ __forceinline__ void cpa16(void* s, const void* g) {
    unsigned sa = (unsigned)__cvta_generic_to_shared(s);
    asm volatile("cp.async.cg.shared.global [%0], [%1], 16;" :: "r"(sa), "l"(g));
}

__global__ void __launch_bounds__(256) qkv_gemm(
    const float* __restrict__ bq, const float* __restrict__ bk,
    const float* __restrict__ bv)
{
    extern __shared__ __align__(16) unsigned char smem_raw[];
    __half (*As)[BM][PA] = reinterpret_cast<__half (*)[BM][PA]>(smem_raw);
    __half (*Bs)[BK][PB] = reinterpret_cast<__half (*)[BK][PB]>(smem_raw + A_BYTES);
    float (*Cs)[PC]      = reinterpret_cast<float (*)[PC]>(smem_raw);

    const int z = blockIdx.z;
    const __half* W   = g_Wh + (size_t)z * HD * HD;
    const float* bias = (z == 0) ? bq : (z == 1) ? bk : bv;
    __half* Ch        = (z == 0) ? g_Qh : (z == 1) ? g_Kh : g_Vh;

    const int tid  = threadIdx.x;
    const int warp = tid >> 5;
    const int wm   = (warp >> 1) * 32;
    const int wn   = (warp & 1) * 64;
    const int rowBase = blockIdx.x * BM;
    const int colBase = blockIdx.y * BN;

    wmma::fragment<wmma::accumulator, 16, 16, 16, float> cf[2][4];
    #pragma unroll
    for (int i = 0; i < 2; i++)
        #pragma unroll
        for (int j = 0; j < 4; j++)
            wmma::fill_fragment(cf[i][j], 0.0f);

    auto load_tiles = [&](int buf, int k0) {
        #pragma unroll
        for (int q = 0; q < 2; q++) {
            int idx = tid + 256 * q;
            int m = idx >> 2, c = idx & 3;
            cpa16(&As[buf][m][8 * c],
                  &g_Xh[(size_t)(rowBase + m) * HD + k0 + 8 * c]);
        }
        #pragma unroll
        for (int q = 0; q < 2; q++) {
            int idx = tid + 256 * q;
            int kk = idx >> 4, c = idx & 15;
            cpa16(&Bs[buf][kk][8 * c],
                  &W[(size_t)(k0 + kk) * HD + colBase + 8 * c]);
        }
        asm volatile("cp.async.commit_group;");
    };

    load_tiles(0, 0);

    const int NIT = HD / BK;
    for (int it = 0; it < NIT; ++it) {
        const int buf = it & 1;
        if (it + 1 < NIT) {
            load_tiles(buf ^ 1, (it + 1) * BK);
            asm volatile("cp.async.wait_group 1;");
        } else {
            asm volatile("cp.async.wait_group 0;");
        }
        __syncthreads();

        #pragma unroll
        for (int kk = 0; kk < BK; kk += 16) {
            wmma::fragment<wmma::matrix_a, 16, 16, 16, __half, wmma::row_major> a[2];
            wmma::fragment<wmma::matrix_b, 16, 16, 16, __half, wmma::row_major> b[4];
            wmma::load_matrix_sync(a[0], &As[buf][wm][kk], PA);
            wmma::load_matrix_sync(a[1], &As[buf][wm + 16][kk], PA);
            #pragma unroll
            for (int j = 0; j < 4; j++)
                wmma::load_matrix_sync(b[j], &Bs[buf][kk][wn + 16 * j], PB);
            #pragma unroll
            for (int i = 0; i < 2; i++)
                #pragma unroll
                for (int j = 0; j < 4; j++)
                    wmma::mma_sync(cf[i][j], a[i], b[j], cf[i][j]);
        }
        __syncthreads();
    }

    #pragma unroll
    for (int i = 0; i < 2; i++)
        #pragma unroll
        for (int j = 0; j < 4; j++)
            wmma::store_matrix_sync(&Cs[wm + 16 * i][wn + 16 * j], cf[i][j], PC,
                                    wmma::mem_row_major);
    __syncthreads();

    #pragma unroll
    for (int q = 0; q < 16; q++) {
        int idx = tid + 256 * q;
        int m = idx >> 5, c = idx & 31;
        float4 v  = *(const float4*)&Cs[m][4 * c];
        float4 bb = *(const float4*)&bias[colBase + 4 * c];
        __half2 h0 = __floats2half2_rn(v.x + bb.x, v.y + bb.y);
        __half2 h1 = __floats2half2_rn(v.z + bb.z, v.w + bb.w);
        __half2* dst = (__half2*)&Ch[(size_t)(rowBase + m) * HD + colBase + 4 * c];
        dst[0] = h0;
        dst[1] = h1;
    }
}

// ---------------------------------------------------------------------------
// Kernel 2: fully fused banded attention. In permuted coords (i = 7t mod 256,
// j = 1+7u mod 256) the graph is a sliding window of 32. One CTA =
// (32-row ttile, head, batch), 256 threads / 8 warps.
//   GEMM0: S2 = Qp @ Ek^T      (r-term table)
//   GEMM1: S  = Qp @ Kp^T      (node term)
//   band softmax (+S2 lookup) -> A (band matrix), P (attn binned by r)
//   GEMM2+3: O = A @ Vp + P @ Ev
// Ek smem buffer is reloaded with Ev (cp.async) overlapped with softmax.
// ---------------------------------------------------------------------------
// smem offsets (bytes)
#define BO_Q    0                      // [32][72] half  (dead after GEMM0/1)
#define BO_K    4608                   // [64][72] half  (dead after GEMM1)
#define BO_V    13824                  // [64][72] half
#define BO_E    23040                  // [64][72] half  (Ek, then Ev)
#define BO_A    32256                  // [32][72] half
#define BO_S2   36864                  // [32][68] float
#define BO_P    45568                  // [32][64] float; later [32][72] half
#define BO_RK   53760                  // [32][32] uint8
#define BAND_SMEM 54784
#define BO_S    BO_Q                   // Sf [32][68] float aliases Qs+Ks

__global__ __launch_bounds__(256) void banded_attn(
    const int* __restrict__ ej, const int* __restrict__ er,
    float* __restrict__ out)
{
    extern __shared__ __align__(16) unsigned char sm[];
    __half (*Qs)[72]  = (__half(*)[72])(sm + BO_Q);
    __half (*Ks)[72]  = (__half(*)[72])(sm + BO_K);
    __half (*Vs)[72]  = (__half(*)[72])(sm + BO_V);
    __half (*Es)[72]  = (__half(*)[72])(sm + BO_E);
    __half (*Ah)[72]  = (__half(*)[72])(sm + BO_A);
    float (*S2s)[68]  = (float(*)[68])(sm + BO_S2);
    float (*Pb)[64]   = (float(*)[64])(sm + BO_P);
    __half (*Ps)[72]  = (__half(*)[72])(sm + BO_P);
    unsigned char* rk = (unsigned char*)(sm + BO_RK);
    float (*Sf)[68]   = (float(*)[68])(sm + BO_S);

    const int tid  = threadIdx.x;
    const int warp = tid >> 5;
    const int t0 = blockIdx.x * 32;
    const int h  = blockIdx.y;
    const int b  = blockIdx.z;

    // ---- stage Q (32x8 uint4), K/V (64x8 each), Ek (64x8), head slice ----
    {
        int tp = tid >> 3, c = tid & 7;
        if (tid < 256) {   // Q: 256 chunks
            int i = (7 * (t0 + tp)) & 255;
            *(uint4*)&Qs[tp][8 * c] =
                *(const uint4*)&g_Qh[(size_t)(b * 256 + i) * HD + h * 64 + 8 * c];
        }
    }
    #pragma unroll
    for (int q = 0; q < 2; q++) {
        int idx = tid + 256 * q;          // 512 = 64*8
        int uc = idx >> 3, c = idx & 7;
        int j = (1 + 7 * (t0 + uc)) & 255;
        const size_t go = (size_t)(b * 256 + j) * HD + h * 64 + 8 * c;
        *(uint4*)&Ks[uc][8 * c] = *(const uint4*)&g_Kh[go];
        *(uint4*)&Vs[uc][8 * c] = *(const uint4*)&g_Vh[go];
    }
    #pragma unroll
    for (int q = 0; q < 2; q++) {
        int idx = tid + 256 * q;          // 512 = 64*8
        int r = idx >> 3, c = idx & 7;
        *(uint4*)&Es[r][8 * c] = *(const uint4*)&g_Ekh[(size_t)r * HD + h * 64 + 8 * c];
    }
    // ---- edge decode: band position + r per (t', d) ----
    #pragma unroll
    for (int q = 0; q < 4; q++) {
        int idx = tid + 256 * q;          // 1024 = 32*32
        int tp = idx >> 5, d = idx & 31;
        int t = t0 + tp;
        int i = (7 * t) & 255;
        int e = (b * 256 + i) * DEG + d;
        int jv = ej[e];
        int u = (183 * (jv - 1)) & 255;   // 7^-1 = 183 mod 256
        int k = (u - t) & 255;            // in [0,32)
        rk[tp * 32 + k] = (unsigned char)er[e];
    }
    // ---- zero A and P ----
    {
        int idx = tid;                    // 288 uint4 = 32*72 halves
        ((uint4*)Ah)[idx] = make_uint4(0, 0, 0, 0);
        if (idx < 32) ((uint4*)Ah)[256 + idx] = make_uint4(0, 0, 0, 0);
        ((uint4*)Pb)[idx] = make_uint4(0, 0, 0, 0);
        ((uint4*)Pb)[256 + idx] = make_uint4(0, 0, 0, 0);
    }
    __syncthreads();

    // ---- GEMM0 + GEMM1: warp w owns 16x16 tile (m0, n0) of 32x64 output ----
    const int m0 = (warp & 1) * 16;
    const int n0 = (warp >> 1) * 16;
    wmma::fragment<wmma::accumulator, 16, 16, 16, float> acc0, acc1;
    wmma::fill_fragment(acc0, 0.0f);
    wmma::fill_fragment(acc1, 0.0f);
    #pragma unroll
    for (int k0 = 0; k0 < 64; k0 += 16) {
        wmma::fragment<wmma::matrix_a, 16, 16, 16, __half, wmma::row_major> a;
        wmma::fragment<wmma::matrix_b, 16, 16, 16, __half, wmma::col_major> b0, b1;
        wmma::load_matrix_sync(a, &Qs[m0][k0], 72);
        wmma::load_matrix_sync(b0, &Es[n0][k0], 72);
        wmma::load_matrix_sync(b1, &Ks[n0][k0], 72);
        wmma::mma_sync(acc0, a, b0, acc0);
        wmma::mma_sync(acc1, a, b1, acc1);
    }
    __syncthreads();   // Qs/Ks reads done; Sf may now alias them
    wmma::store_matrix_sync(&S2s[m0][n0], acc0, 68, wmma::mem_row_major);
    wmma::store_matrix_sync(&Sf[m0][n0], acc1, 68, wmma::mem_row_major);
    __syncthreads();

    // ---- reload Es with Ev via cp.async (overlaps softmax) ----
    #pragma unroll
    for (int q = 0; q < 2; q++) {
        int idx = tid + 256 * q;
        int r = idx >> 3, c = idx & 7;
        cpa16(&Es[r][8 * c], &g_Evh[(size_t)r * HD + h * 64 + 8 * c]);
    }
    asm volatile("cp.async.commit_group;");

    // ---- band softmax: 8 threads per row, 4 k each ----
    {
        const int tp = tid >> 3, qd = tid & 7;
        float ex[4];
        int rr[4];
        float mx = -1e30f;
        #pragma unroll
        for (int zl = 0; zl < 4; zl++) {
            int k = qd * 4 + zl;
            rr[zl] = rk[tp * 32 + k];
            ex[zl] = (Sf[tp][tp + k] + S2s[tp][rr[zl]]) * 0.125f;
            mx = fmaxf(mx, ex[zl]);
        }
        mx = fmaxf(mx, __shfl_xor_sync(0xffffffffu, mx, 1));
        mx = fmaxf(mx, __shfl_xor_sync(0xffffffffu, mx, 2));
        mx = fmaxf(mx, __shfl_xor_sync(0xffffffffu, mx, 4));
        float sum = 0.f;
        #pragma unroll
        for (int zl = 0; zl < 4; zl++) {
            ex[zl] = __expf(ex[zl] - mx);
            sum += ex[zl];
        }
        sum += __shfl_xor_sync(0xffffffffu, sum, 1);
        sum += __shfl_xor_sync(0xffffffffu, sum, 2);
        sum += __shfl_xor_sync(0xffffffffu, sum, 4);
        const float inv = 1.0f / sum;
        #pragma unroll
        for (int zl = 0; zl < 4; zl++) {
            int k = qd * 4 + zl;
            float a = ex[zl] * inv;
            Ah[tp][tp + k] = __float2half(a);
            atomicAdd(&Pb[tp][rr[zl]], a);
        }
    }
    __syncthreads();

    // ---- P fp32 -> fp16 in place (reg-staged) ----
    {
        const int tp = tid >> 3, c = tid & 7;     // 8 floats per thread
        float pv[8];
        #pragma unroll
        for (int zl = 0; zl < 8; zl++) pv[zl] = Pb[tp][c * 8 + zl];
        __syncthreads();
        #pragma unroll
        for (int zl = 0; zl < 4; zl++)
            *(__half2*)&Ps[tp][c * 8 + 2 * zl] =
                __floats2half2_rn(pv[2 * zl], pv[2 * zl + 1]);
    }
    asm volatile("cp.async.wait_group 0;");
    __syncthreads();

    // ---- GEMM2 + GEMM3: O = A @ V + P @ Ev ----
    wmma::fragment<wmma::accumulator, 16, 16, 16, float> acc;
    wmma::fill_fragment(acc, 0.0f);
    #pragma unroll
    for (int k0 = 0; k0 < 64; k0 += 16) {
        wmma::fragment<wmma::matrix_a, 16, 16, 16, __half, wmma::row_major> a0, a1;
        wmma::fragment<wmma::matrix_b, 16, 16, 16, __half, wmma::row_major> b0, b1;
        wmma::load_matrix_sync(a0, &Ah[m0][k0], 72);
        wmma::load_matrix_sync(b0, &Vs[k0][n0], 72);
        wmma::mma_sync(acc, a0, b0, acc);
        wmma::load_matrix_sync(a1, &Ps[m0][k0], 72);
        wmma::load_matrix_sync(b1, &Es[k0][n0], 72);
        wmma::mma_sync(acc, a1, b1, acc);
    }
    __syncthreads();
    wmma::store_matrix_sync(&Sf[m0][n0], acc, 68, wmma::mem_row_major);
    __syncthreads();

    // ---- write out (permuted rows) ----
    #pragma unroll
    for (int q = 0; q < 2; q++) {
        int idx = tid + 256 * q;          // 512 = 32*16 float4
        int tp = idx >> 4, c = idx & 15;
        int i = (7 * (t0 + tp)) & 255;
        float4 v = *(const float4*)&Sf[tp][4 * c];
        *(float4*)&out[(size_t)(b * 256 + i) * HD + h * 64 + 4 * c] = v;
    }
}

// ---------------------------------------------------------------------------
extern "C" void kernel_launch(void* const* d_in, const int* in_sizes, int n_in,
                              void* d_out, int out_size)
{
    const float* x  = (const float*)d_in[0];
    const int* edges = (const int*)d_in[1];
    const float* Wq = (const float*)d_in[2];
    const float* bq = (const float*)d_in[3];
    const float* Wk = (const float*)d_in[4];
    const float* bk = (const float*)d_in[5];
    const float* Wv = (const float*)d_in[6];
    const float* bv = (const float*)d_in[7];
    const float* Ek = (const float*)d_in[8];
    const float* Ev = (const float*)d_in[9];
    float* out = (float*)d_out;

    const size_t E = (size_t)in_sizes[1] / 4;

    cudaFuncSetAttribute(qkv_gemm, cudaFuncAttributeMaxDynamicSharedMemorySize,
                         GEMM_SMEM);
    cudaFuncSetAttribute(banded_attn, cudaFuncAttributeMaxDynamicSharedMemorySize,
                         BAND_SMEM);

    cvt_f2h<<<dim3(576, 8), 256>>>(x, Wq, Wk, Wv, Ek, Ev);

    dim3 ggrid(NNODES / BM, HD / BN, 3);
    qkv_gemm<<<ggrid, 256, GEMM_SMEM>>>(bq, bk, bv);

    banded_attn<<<dim3(NPB / 32, NH, 8), 256, BAND_SMEM>>>(
        edges + 2 * E, edges + 3 * E, out);
}